// round 1
// baseline (speedup 1.0000x reference)
#include <cuda_runtime.h>
#include <math.h>

#define BATCH 8
#define SEQ   2048
#define DIN   1024
#define DHEAD 128
#define NROWS (BATCH * SEQ)

// scratch for Q/K/V projections (8 MB each)
__device__ float g_Q[NROWS * DHEAD];
__device__ float g_K[NROWS * DHEAD];
__device__ float g_V[NROWS * DHEAD];

// ---------------------------------------------------------------------------
// Projection: out = X @ W + b for W in {Wq, Wk, Wv}; blockIdx.y selects matrix.
// Tile: 64 rows x 128 cols per block, 256 threads, k-step 16.
// ---------------------------------------------------------------------------
__global__ __launch_bounds__(256) void proj_kernel(
    const float* __restrict__ X,
    const float* __restrict__ Wq, const float* __restrict__ bq,
    const float* __restrict__ Wk, const float* __restrict__ bk,
    const float* __restrict__ Wv, const float* __restrict__ bv)
{
    const float* W; const float* bias; float* out;
    if (blockIdx.y == 0)      { W = Wq; bias = bq; out = g_Q; }
    else if (blockIdx.y == 1) { W = Wk; bias = bk; out = g_K; }
    else                      { W = Wv; bias = bv; out = g_V; }

    __shared__ float Xs[64][16];
    __shared__ float Ws[16][128];

    const int tid = threadIdx.x;
    const int tx = tid & 31;          // 0..31 -> 4 output cols each
    const int ty = tid >> 5;          // 0..7  -> 8 output rows each
    const int row0 = blockIdx.x * 64;

    float acc[8][4];
    #pragma unroll
    for (int i = 0; i < 8; i++)
        #pragma unroll
        for (int j = 0; j < 4; j++) acc[i][j] = 0.f;

    const int xr = tid >> 2;          // 0..63
    const int xc = (tid & 3) * 4;     // 0,4,8,12

    for (int k = 0; k < DIN; k += 16) {
        *(float4*)&Xs[xr][xc] =
            *(const float4*)&X[(size_t)(row0 + xr) * DIN + k + xc];
        #pragma unroll
        for (int l = 0; l < 2; l++) {
            int e  = tid + l * 256;          // 0..511 float4 slots
            int r  = e >> 5;
            int c4 = (e & 31) * 4;
            *(float4*)&Ws[r][c4] = *(const float4*)&W[(size_t)(k + r) * DHEAD + c4];
        }
        __syncthreads();
        #pragma unroll
        for (int kk = 0; kk < 16; kk++) {
            float4 b4 = *(const float4*)&Ws[kk][tx * 4];
            #pragma unroll
            for (int i = 0; i < 8; i++) {
                float a = Xs[ty * 8 + i][kk];
                acc[i][0] += a * b4.x;
                acc[i][1] += a * b4.y;
                acc[i][2] += a * b4.z;
                acc[i][3] += a * b4.w;
            }
        }
        __syncthreads();
    }

    float4 bb = *(const float4*)&bias[tx * 4];
    #pragma unroll
    for (int i = 0; i < 8; i++) {
        float4 o;
        o.x = acc[i][0] + bb.x;
        o.y = acc[i][1] + bb.y;
        o.z = acc[i][2] + bb.z;
        o.w = acc[i][3] + bb.w;
        *(float4*)&out[(size_t)(row0 + ty * 8 + i) * DHEAD + tx * 4] = o;
    }
}

// ---------------------------------------------------------------------------
// Flash-style causal attention with dropout-mask on probabilities.
// Block: one (batch, 64-query tile). 256 threads.
// Online softmax: m,l track UNMASKED exp stats; numerator uses mask*p.
// Reference quirks honored: causal zeros -> -inf, plus (w == 0) -> -inf.
// ---------------------------------------------------------------------------
#define QS_STRIDE 132   // float4-aligned rows, conflict-free LDS128
#define KS_STRIDE 129   // scalar reads across rows: 2-way conflicts only
#define VS_STRIDE 132
#define PS_STRIDE 68

#define SMEM_FLOATS (64*QS_STRIDE + 64*KS_STRIDE + 64*VS_STRIDE + 64*PS_STRIDE + 192)

__global__ __launch_bounds__(256) void attn_kernel(
    const float* __restrict__ drop_mask, float* __restrict__ out)
{
    extern __shared__ float sm[];
    float* Qs      = sm;                          // [64][132]
    float* Ks      = Qs + 64 * QS_STRIDE;         // [64][129]
    float* Vs      = Ks + 64 * KS_STRIDE;         // [64][132]
    float* Ps      = Vs + 64 * VS_STRIDE;         // [64][68]
    float* m_s     = Ps + 64 * PS_STRIDE;         // [64]
    float* l_s     = m_s + 64;                    // [64]
    float* scale_s = l_s + 64;                    // [64]

    const int tid = threadIdx.x;
    const int qt  = 31 - (int)blockIdx.x;         // big tiles first (load balance)
    const int bb  = blockIdx.y;
    const int q0  = qt * 64;
    const size_t batch_off = (size_t)bb * SEQ * DHEAD;

    // S-compute layout: 16x16 threads, 4x4 scores each
    const int tx4 = tid & 15;
    const int ty4 = tid >> 4;
    // PV/output layout: 8x32 threads, 8 rows x 4 cols each
    const int txo = tid & 31;
    const int tyo = tid >> 5;

    if (tid < 64) { m_s[tid] = -INFINITY; l_s[tid] = 0.f; }

    // load Q tile
    #pragma unroll
    for (int it = 0; it < 8; it++) {
        int idx = tid + it * 256;
        int t = idx >> 5, c4 = (idx & 31) * 4;
        *(float4*)&Qs[t * QS_STRIDE + c4] =
            *(const float4*)&g_Q[batch_off + (size_t)(q0 + t) * DHEAD + c4];
    }

    float acc[8][4];
    #pragma unroll
    for (int i = 0; i < 8; i++)
        #pragma unroll
        for (int j = 0; j < 4; j++) acc[i][j] = 0.f;

    for (int kt = 0; kt <= qt; kt++) {
        const int k0 = kt * 64;

        // load K (scalar scatter into pad-129 rows) and V (float4, pad-132)
        #pragma unroll
        for (int it = 0; it < 8; it++) {
            int idx = tid + it * 256;
            int t = idx >> 5, c4 = (idx & 31) * 4;
            float4 kv = *(const float4*)&g_K[batch_off + (size_t)(k0 + t) * DHEAD + c4];
            Ks[t * KS_STRIDE + c4 + 0] = kv.x;
            Ks[t * KS_STRIDE + c4 + 1] = kv.y;
            Ks[t * KS_STRIDE + c4 + 2] = kv.z;
            Ks[t * KS_STRIDE + c4 + 3] = kv.w;
            *(float4*)&Vs[t * VS_STRIDE + c4] =
                *(const float4*)&g_V[batch_off + (size_t)(k0 + t) * DHEAD + c4];
        }
        __syncthreads();

        // ---- S = Q @ K^T (64x64), 4x4 per thread ----
        float s[4][4];
        #pragma unroll
        for (int i = 0; i < 4; i++)
            #pragma unroll
            for (int j = 0; j < 4; j++) s[i][j] = 0.f;

        #pragma unroll 8
        for (int d = 0; d < DHEAD; d++) {
            float bv0 = Ks[(tx4 * 4 + 0) * KS_STRIDE + d];
            float bv1 = Ks[(tx4 * 4 + 1) * KS_STRIDE + d];
            float bv2 = Ks[(tx4 * 4 + 2) * KS_STRIDE + d];
            float bv3 = Ks[(tx4 * 4 + 3) * KS_STRIDE + d];
            #pragma unroll
            for (int i = 0; i < 4; i++) {
                float a = Qs[(ty4 * 4 + i) * QS_STRIDE + d];
                s[i][0] += a * bv0;
                s[i][1] += a * bv1;
                s[i][2] += a * bv2;
                s[i][3] += a * bv3;
            }
        }

        // ---- masking: causal (-inf above diagonal) and exact-zero -> -inf ----
        #pragma unroll
        for (int i = 0; i < 4; i++) {
            int qrow = q0 + ty4 * 4 + i;
            #pragma unroll
            for (int j = 0; j < 4; j++) {
                int kcol = k0 + tx4 * 4 + j;
                if (kcol > qrow || s[i][j] == 0.0f) s[i][j] = -INFINITY;
            }
        }

        // ---- online softmax update ----
        float mt[4];
        #pragma unroll
        for (int i = 0; i < 4; i++)
            mt[i] = fmaxf(fmaxf(s[i][0], s[i][1]), fmaxf(s[i][2], s[i][3]));
        #pragma unroll
        for (int off = 1; off < 16; off <<= 1)
            #pragma unroll
            for (int i = 0; i < 4; i++)
                mt[i] = fmaxf(mt[i], __shfl_xor_sync(0xffffffffu, mt[i], off));

        float m_old[4], m_new[4];
        #pragma unroll
        for (int i = 0; i < 4; i++) {
            m_old[i] = m_s[ty4 * 4 + i];
            m_new[i] = fmaxf(m_old[i], mt[i]);
        }

        float p[4][4], rs[4];
        #pragma unroll
        for (int i = 0; i < 4; i++) {
            #pragma unroll
            for (int j = 0; j < 4; j++) p[i][j] = __expf(s[i][j] - m_new[i]);
            rs[i] = (p[i][0] + p[i][1]) + (p[i][2] + p[i][3]);
        }
        #pragma unroll
        for (int off = 1; off < 16; off <<= 1)
            #pragma unroll
            for (int i = 0; i < 4; i++)
                rs[i] += __shfl_xor_sync(0xffffffffu, rs[i], off);

        __syncwarp();
        if (tx4 == 0) {
            #pragma unroll
            for (int i = 0; i < 4; i++) {
                int r = ty4 * 4 + i;
                float sc = __expf(m_old[i] - m_new[i]);
                scale_s[r] = sc;
                l_s[r]     = l_s[r] * sc + rs[i];
                m_s[r]     = m_new[i];
            }
        }

        // ---- apply dropout mask, stage P into smem ----
        #pragma unroll
        for (int i = 0; i < 4; i++) {
            int qrow = q0 + ty4 * 4 + i;
            float4 mk = *(const float4*)&drop_mask[
                ((size_t)bb * SEQ + qrow) * SEQ + k0 + tx4 * 4];
            float4 pw;
            pw.x = p[i][0] * mk.x;
            pw.y = p[i][1] * mk.y;
            pw.z = p[i][2] * mk.z;
            pw.w = p[i][3] * mk.w;
            *(float4*)&Ps[(ty4 * 4 + i) * PS_STRIDE + tx4 * 4] = pw;
        }
        __syncthreads();

        // ---- rescale accumulators, O += P @ V ----
        float scl[8];
        #pragma unroll
        for (int i = 0; i < 8; i++) scl[i] = scale_s[tyo * 8 + i];
        #pragma unroll
        for (int i = 0; i < 8; i++)
            #pragma unroll
            for (int j = 0; j < 4; j++) acc[i][j] *= scl[i];

        #pragma unroll 4
        for (int t = 0; t < 64; t++) {
            float4 v4 = *(const float4*)&Vs[t * VS_STRIDE + txo * 4];
            #pragma unroll
            for (int i = 0; i < 8; i++) {
                float a = Ps[(tyo * 8 + i) * PS_STRIDE + t];
                acc[i][0] += a * v4.x;
                acc[i][1] += a * v4.y;
                acc[i][2] += a * v4.z;
                acc[i][3] += a * v4.w;
            }
        }
        __syncthreads();
    }

    // ---- finalize: divide by softmax denominator, write out ----
    #pragma unroll
    for (int i = 0; i < 8; i++) {
        float inv = 1.0f / l_s[tyo * 8 + i];
        float4 o;
        o.x = acc[i][0] * inv;
        o.y = acc[i][1] * inv;
        o.z = acc[i][2] * inv;
        o.w = acc[i][3] * inv;
        *(float4*)&out[batch_off + (size_t)(q0 + tyo * 8 + i) * DHEAD + txo * 4] = o;
    }
}

// ---------------------------------------------------------------------------
extern "C" void kernel_launch(void* const* d_in, const int* in_sizes, int n_in,
                              void* d_out, int out_size)
{
    const float* X  = (const float*)d_in[0];
    const float* Wq = (const float*)d_in[1];
    const float* bq = (const float*)d_in[2];
    const float* Wk = (const float*)d_in[3];
    const float* bk = (const float*)d_in[4];
    const float* Wv = (const float*)d_in[5];
    const float* bv = (const float*)d_in[6];
    const float* dm = (const float*)d_in[7];
    float* out = (float*)d_out;

    dim3 g1(NROWS / 64, 3);
    proj_kernel<<<g1, 256>>>(X, Wq, bq, Wk, bk, Wv, bv);

    const size_t smem_bytes = (size_t)SMEM_FLOATS * sizeof(float);  // ~116 KB
    cudaFuncSetAttribute(attn_kernel,
                         cudaFuncAttributeMaxDynamicSharedMemorySize,
                         (int)smem_bytes);
    dim3 g2(32, BATCH);
    attn_kernel<<<g2, 256, smem_bytes>>>(dm, out);
}